// round 16
// baseline (speedup 1.0000x reference)
#include <cuda_runtime.h>
#include <cuda_fp16.h>
#include <cstdint>

// EuclideanDistance: mat_1 [8192,128] f32, mat_2 [8192,128] f32 -> out [8192,8192] f32
// D[i,j] = ||a_i||^2 + ||b_j||^2 - 2 * (A B^T)[i,j]
// R15: legacy mma.sync is issue-rate-walled at ~20cyc/instr/SMSP (R8/R9/R11 all
// 21.4-22.0). Only lever: fewer instructions. K-split GEMM:
//   dims 0..63  -> int8 m16n8k32 (per-row scales, exact s32 accum)   [2 ksteps]
//   dims 64..127-> fp16 m16n8k16 (f32 accum)                          [4 ksteps]
// 192 MMAs/warp/tile vs 256 pure-fp16 (75%). Norms exact f32. Predicted rel ~6e-4.

#define NR 8192
#define DK 128
#define NTH 128

__device__ float g_sq1[NR];
__device__ float g_sq2[NR];
__device__ float g_rsa[NR];            // per-row 1/scale for A int8 part
__device__ float g_rsb[NR];
__device__ __half g_A16[NR * 64];      // dims 64..127 as fp16
__device__ __half g_B16[NR * 64];
__device__ int8_t g_A8[NR * 64];       // dims 0..63 quantized
__device__ int8_t g_B8[NR * 64];

// ---------------- smem layout ----------------
// fp16 rows: 64 fp16 = 128B + 16B pad = 144 (9x16, odd -> conflict-free ldsm)
// int8 rows: 64 s8 = 64B + 16B pad = 80 (5x16, odd)
#define R16B 144
#define R8B 80
#define SMA16 0
#define SMA8 18432
#define SMB 28672
#define BT16 0
#define BT8 18432
#define BTILE 28672
#define SM_TOTAL (28672 + 2 * 28672)   // 86016 -> 2 CTAs/SM

__device__ __forceinline__ uint32_t smem_u32(const void* p) {
    uint32_t a;
    asm("{ .reg .u64 t; cvta.to.shared.u64 t, %1; cvt.u32.u64 %0, t; }" : "=r"(a) : "l"(p));
    return a;
}

__device__ __forceinline__ void cpa16(uint32_t saddr, const void* gaddr) {
    asm volatile("cp.async.cg.shared.global [%0], [%1], 16;" :: "r"(saddr), "l"(gaddr));
}
__device__ __forceinline__ void cpa_commit() {
    asm volatile("cp.async.commit_group;" ::: "memory");
}

#define LDSM_X4(r0, r1, r2, r3, addr) \
    asm volatile("ldmatrix.sync.aligned.m8n8.x4.shared.b16 {%0,%1,%2,%3}, [%4];" \
                 : "=r"(r0), "=r"(r1), "=r"(r2), "=r"(r3) : "r"(addr))

#define MMA_F16(c, a0, a1, a2, a3, b0, b1) \
    asm volatile("mma.sync.aligned.m16n8k16.row.col.f32.f16.f16.f32 " \
                 "{%0,%1,%2,%3}, {%4,%5,%6,%7}, {%8,%9}, {%0,%1,%2,%3};" \
                 : "+f"((c)[0]), "+f"((c)[1]), "+f"((c)[2]), "+f"((c)[3]) \
                 : "r"(a0), "r"(a1), "r"(a2), "r"(a3), "r"(b0), "r"(b1))

#define MMA_S8(c, a0, a1, a2, a3, b0, b1) \
    asm volatile("mma.sync.aligned.m16n8k32.row.col.s32.s8.s8.s32 " \
                 "{%0,%1,%2,%3}, {%4,%5,%6,%7}, {%8,%9}, {%0,%1,%2,%3};" \
                 : "+r"((c)[0]), "+r"((c)[1]), "+r"((c)[2]), "+r"((c)[3]) \
                 : "r"(a0), "r"(a1), "r"(a2), "r"(a3), "r"(b0), "r"(b1))

// A strips: fp16 128 rows x 8 segs; int8 128 rows x 4 segs
__device__ __forceinline__ void load_a(const __half* __restrict__ a16,
                                       const int8_t* __restrict__ a8,
                                       uint32_t sb, int tid) {
#pragma unroll
    for (int l = 0; l < 8; l++) {
        int idx = tid + NTH * l;
        int row = idx >> 3;
        int seg = idx & 7;
        cpa16(sb + SMA16 + row * R16B + seg * 16, a16 + (size_t)row * 64 + seg * 8);
    }
#pragma unroll
    for (int l = 0; l < 4; l++) {
        int idx = tid + NTH * l;
        int row = idx >> 2;
        int seg = idx & 3;
        cpa16(sb + SMA8 + row * R8B + seg * 16, a8 + (size_t)row * 64 + seg * 16);
    }
}

__device__ __forceinline__ void load_btile(const __half* __restrict__ b16,
                                           const int8_t* __restrict__ b8,
                                           int tt, uint32_t stage, int tid) {
    const __half* s16 = b16 + (size_t)tt * 128 * 64;
    const int8_t* s8 = b8 + (size_t)tt * 128 * 64;
#pragma unroll
    for (int l = 0; l < 8; l++) {
        int idx = tid + NTH * l;
        int row = idx >> 3;
        int seg = idx & 7;
        cpa16(stage + BT16 + row * R16B + seg * 16, s16 + (size_t)row * 64 + seg * 8);
    }
#pragma unroll
    for (int l = 0; l < 4; l++) {
        int idx = tid + NTH * l;
        int row = idx >> 2;
        int seg = idx & 3;
        cpa16(stage + BT8 + row * R8B + seg * 16, s8 + (size_t)row * 64 + seg * 16);
    }
}

__global__ void __launch_bounds__(NTH, 2)
euclid_mma_kernel(const __half* __restrict__ A16, const __half* __restrict__ B16,
                  const int8_t* __restrict__ A8, const int8_t* __restrict__ B8,
                  const float* __restrict__ sq1g, const float* __restrict__ sq2g,
                  const float* __restrict__ rsag, const float* __restrict__ rsbg,
                  float* __restrict__ C) {
    extern __shared__ char smem[];
    const uint32_t sb = smem_u32(smem);
    const int tid = threadIdx.x;
    const int lane = tid & 31;
    const int wid = tid >> 5;
    const int wm = wid & 1;            // 2 warp rows x 64
    const int wn = (wid >> 1) & 1;     // 2 warp cols x 64
    const int m0 = blockIdx.y * 128;
    const int nt0 = blockIdx.x * 2;    // 2 N-tiles (128 wide) per CTA

    // Prologue: A strips + B tile 0 -> group0; B tile 1 -> group1. All resident.
    load_a(A16 + (size_t)m0 * 64, A8 + (size_t)m0 * 64, sb, tid);
    load_btile(B16, B8, nt0, sb + SMB + 0 * BTILE, tid);
    cpa_commit();
    load_btile(B16, B8, nt0 + 1, sb + SMB + 1 * BTILE, tid);
    cpa_commit();

    // per-thread row context (fixed for whole CTA)
    float s1r[4][2], ra[4][2];
#pragma unroll
    for (int mf = 0; mf < 4; mf++) {
        int m = m0 + wm * 64 + mf * 16 + (lane >> 2);
        s1r[mf][0] = sq1g[m];
        s1r[mf][1] = sq1g[m + 8];
        ra[mf][0] = rsag[m];
        ra[mf][1] = rsag[m + 8];
    }

    // ldmatrix addresses
    uint32_t aAddr16[4], aAddr8[4];
#pragma unroll
    for (int mf = 0; mf < 4; mf++) {
        int r = wm * 64 + mf * 16 + (lane & 15);
        uint32_t col = (uint32_t)((lane >> 4) << 4);
        aAddr16[mf] = sb + SMA16 + r * R16B + col;
        aAddr8[mf] = sb + SMA8 + r * R8B + col;
    }
    uint32_t bOff16[4], bOff8[4];
#pragma unroll
    for (int p = 0; p < 4; p++) {
        int r = wn * 64 + p * 16 + ((lane >> 4) & 1) * 8 + (lane & 7);
        uint32_t col = (uint32_t)(((lane >> 3) & 1) << 4);
        bOff16[p] = r * R16B + col;
        bOff8[p] = r * R8B + col;
    }

#pragma unroll
    for (int t = 0; t < 2; t++) {
        if (t == 0) asm volatile("cp.async.wait_group 1;" ::: "memory");
        else        asm volatile("cp.async.wait_group 0;" ::: "memory");
        __syncthreads();

        const uint32_t stage = sb + SMB + (uint32_t)t * BTILE;
        const int nb = (nt0 + t) * 128 + wn * 64;

        // column context for this tile
        float s2r[8][2], rb[8][2];
#pragma unroll
        for (int nf = 0; nf < 8; nf++) {
            int n = nb + nf * 8 + 2 * (lane & 3);
            s2r[nf][0] = sq2g[n];
            s2r[nf][1] = sq2g[n + 1];
            rb[nf][0] = rsbg[n];
            rb[nf][1] = rsbg[n + 1];
        }

        // ---- Phase 1: int8 (dims 0..63), 2 k32-steps, s32 accum ----
        int acc8[4][8][4];
#pragma unroll
        for (int mf = 0; mf < 4; mf++)
#pragma unroll
            for (int nf = 0; nf < 8; nf++)
#pragma unroll
                for (int q = 0; q < 4; q++) acc8[mf][nf][q] = 0;

#pragma unroll
        for (int ks = 0; ks < 2; ks++) {
            uint32_t a[4][4], bf[8][2];
#pragma unroll
            for (int mf = 0; mf < 4; mf++)
                LDSM_X4(a[mf][0], a[mf][1], a[mf][2], a[mf][3],
                        aAddr8[mf] + ks * 32);
#pragma unroll
            for (int p = 0; p < 4; p++)
                LDSM_X4(bf[p * 2][0], bf[p * 2][1], bf[p * 2 + 1][0],
                        bf[p * 2 + 1][1], stage + BT8 + bOff8[p] + ks * 32);
#pragma unroll
            for (int mf = 0; mf < 4; mf++)
#pragma unroll
                for (int nf = 0; nf < 8; nf++)
                    MMA_S8(acc8[mf][nf], a[mf][0], a[mf][1], a[mf][2], a[mf][3],
                           bf[nf][0], bf[nf][1]);
        }

        // convert int8 dot to f32 with per-row x per-col scales
        float acc[4][8][4];
#pragma unroll
        for (int mf = 0; mf < 4; mf++)
#pragma unroll
            for (int nf = 0; nf < 8; nf++) {
                float s00 = ra[mf][0] * rb[nf][0];
                float s01 = ra[mf][0] * rb[nf][1];
                float s10 = ra[mf][1] * rb[nf][0];
                float s11 = ra[mf][1] * rb[nf][1];
                acc[mf][nf][0] = (float)acc8[mf][nf][0] * s00;
                acc[mf][nf][1] = (float)acc8[mf][nf][1] * s01;
                acc[mf][nf][2] = (float)acc8[mf][nf][2] * s10;
                acc[mf][nf][3] = (float)acc8[mf][nf][3] * s11;
            }

        // ---- Phase 2: fp16 (dims 64..127), 4 k16-steps into f32 acc ----
#pragma unroll
        for (int ks = 0; ks < 4; ks++) {
            uint32_t a[4][4], bf[8][2];
#pragma unroll
            for (int mf = 0; mf < 4; mf++)
                LDSM_X4(a[mf][0], a[mf][1], a[mf][2], a[mf][3],
                        aAddr16[mf] + ks * 32);
#pragma unroll
            for (int p = 0; p < 4; p++)
                LDSM_X4(bf[p * 2][0], bf[p * 2][1], bf[p * 2 + 1][0],
                        bf[p * 2 + 1][1], stage + BT16 + bOff16[p] + ks * 32);
#pragma unroll
            for (int mf = 0; mf < 4; mf++)
#pragma unroll
                for (int nf = 0; nf < 8; nf++)
                    MMA_F16(acc[mf][nf], a[mf][0], a[mf][1], a[mf][2], a[mf][3],
                            bf[nf][0], bf[nf][1]);
        }

        // Epilogue: D = sq1 + sq2 - 2*dot; streaming stores (write-once)
#pragma unroll
        for (int mf = 0; mf < 4; mf++) {
            size_t m = (size_t)(m0 + wm * 64 + mf * 16 + (lane >> 2));
#pragma unroll
            for (int nf = 0; nf < 8; nf++) {
                int n = nb + nf * 8 + 2 * (lane & 3);
                float2 o0, o1;
                o0.x = fmaf(acc[mf][nf][0], -2.0f, s1r[mf][0] + s2r[nf][0]);
                o0.y = fmaf(acc[mf][nf][1], -2.0f, s1r[mf][0] + s2r[nf][1]);
                o1.x = fmaf(acc[mf][nf][2], -2.0f, s1r[mf][1] + s2r[nf][0]);
                o1.y = fmaf(acc[mf][nf][3], -2.0f, s1r[mf][1] + s2r[nf][1]);
                __stcs(reinterpret_cast<float2*>(C + m * NR + n), o0);
                __stcs(reinterpret_cast<float2*>(C + (m + 8) * NR + n), o1);
            }
        }
    }
}

// Prep: exact f32 row norms; dims 0..63 -> per-row-scaled int8; dims 64..127 -> fp16.
__global__ void prep_kernel(const float* __restrict__ A, const float* __restrict__ B,
                            __half* __restrict__ A16, __half* __restrict__ B16,
                            int8_t* __restrict__ A8, int8_t* __restrict__ B8,
                            float* __restrict__ sq1, float* __restrict__ sq2,
                            float* __restrict__ rsa, float* __restrict__ rsb) {
    int w = (blockIdx.x * blockDim.x + threadIdx.x) >> 5;
    int lane = threadIdx.x & 31;
    const float* src;
    __half* d16;
    int8_t* d8;
    float* nrm;
    float* rs;
    int row;
    if (w < NR) {
        src = A; d16 = A16; d8 = A8; nrm = sq1; rs = rsa; row = w;
    } else {
        src = B; d16 = B16; d8 = B8; nrm = sq2; rs = rsb; row = w - NR;
    }
    float4 v = reinterpret_cast<const float4*>(src + (size_t)row * DK)[lane];

    // exact f32 norm over all 128 dims
    float s = v.x * v.x + v.y * v.y + v.z * v.z + v.w * v.w;
#pragma unroll
    for (int o = 16; o > 0; o >>= 1) s += __shfl_xor_sync(0xffffffffu, s, o);
    if (lane == 0) nrm[row] = s;

    // per-row max over dims 0..63 (lanes 0..15)
    float mx = 0.0f;
    if (lane < 16)
        mx = fmaxf(fmaxf(fabsf(v.x), fabsf(v.y)), fmaxf(fabsf(v.z), fabsf(v.w)));
#pragma unroll
    for (int o = 16; o > 0; o >>= 1) mx = fmaxf(mx, __shfl_xor_sync(0xffffffffu, mx, o));
    mx = fmaxf(mx, 1e-20f);
    float scale = 126.0f / mx;
    if (lane == 0) rs[row] = mx * (1.0f / 126.0f);

    if (lane < 16) {
        // quantize dims 0..63
        int q0 = max(-127, min(127, __float2int_rn(v.x * scale)));
        int q1 = max(-127, min(127, __float2int_rn(v.y * scale)));
        int q2 = max(-127, min(127, __float2int_rn(v.z * scale)));
        int q3 = max(-127, min(127, __float2int_rn(v.w * scale)));
        char4 c4 = make_char4((char)q0, (char)q1, (char)q2, (char)q3);
        *reinterpret_cast<char4*>(d8 + (size_t)row * 64 + lane * 4) = c4;
    } else {
        // fp16 for dims 64..127
        __half2 h01 = __floats2half2_rn(v.x, v.y);
        __half2 h23 = __floats2half2_rn(v.z, v.w);
        uint2 packed;
        packed.x = *reinterpret_cast<uint32_t*>(&h01);
        packed.y = *reinterpret_cast<uint32_t*>(&h23);
        *reinterpret_cast<uint2*>(d16 + (size_t)row * 64 + (lane - 16) * 4) = packed;
    }
}

extern "C" void kernel_launch(void* const* d_in, const int* in_sizes, int n_in,
                              void* d_out, int out_size) {
    const float* A = (const float*)d_in[0];
    const float* B = (const float*)d_in[1];
    float* C = (float*)d_out;

    float *sq1, *sq2, *rsa, *rsb;
    __half *A16, *B16;
    int8_t *A8, *B8;
    cudaGetSymbolAddress((void**)&sq1, g_sq1);
    cudaGetSymbolAddress((void**)&sq2, g_sq2);
    cudaGetSymbolAddress((void**)&rsa, g_rsa);
    cudaGetSymbolAddress((void**)&rsb, g_rsb);
    cudaGetSymbolAddress((void**)&A16, g_A16);
    cudaGetSymbolAddress((void**)&B16, g_B16);
    cudaGetSymbolAddress((void**)&A8, g_A8);
    cudaGetSymbolAddress((void**)&B8, g_B8);

    cudaFuncSetAttribute(euclid_mma_kernel,
                         cudaFuncAttributeMaxDynamicSharedMemorySize, SM_TOTAL);

    prep_kernel<<<2 * NR / 8, 256>>>(A, B, A16, B16, A8, B8, sq1, sq2, rsa, rsb);

    dim3 grid(NR / 128 / 2, NR / 128);  // (32, 64) = 2048 CTAs, 2/SM
    euclid_mma_kernel<<<grid, NTH, SM_TOTAL>>>(A16, B16, A8, B8, sq1, sq2,
                                               rsa, rsb, C);
}